// round 11
// baseline (speedup 1.0000x reference)
#include <cuda_runtime.h>
#include <cfloat>

// N=8192 tokens, K=4096, D=1024.
//   idx[n] = argmax_k x[n,k]  (first-occurrence tie-break)
//   out[n,d] = W[d, idx[n]]
//
// K1: float4 transpose W [D,K] -> g_Wt [K,D], 1024 blocks, PDL trigger.
// K2 (PDL consumer): 2048 blocks x 4 tokens. Each token uses the proven
//     block-wide argmax (256 threads, float4, 75% DRAM structure). All 4
//     argmaxes run pre-barrier (64 KB x-work per block = enough overlap
//     capacity to cover K1's drain), then ONE cudaGridDependencySynchronize,
//     then 4 coalesced row gathers from g_Wt.

#define NTOK 8192
#define KDIM 4096
#define DDIM 1024
#define TP_TILE 64
#define TP_BLOCKS ((KDIM / TP_TILE) * (DDIM / TP_TILE))   // 1024

__device__ float g_Wt[(size_t)KDIM * DDIM];   // 16 MB scratch

// ---------------- K1: transpose, float4 both sides ----------------
__global__ void __launch_bounds__(256) transpose_kernel(const float* __restrict__ W)
{
#if __CUDA_ARCH__ >= 900
    cudaTriggerProgrammaticLaunchCompletion();   // let K2 co-schedule
#endif
    __shared__ float t[TP_TILE][TP_TILE + 1];
    const int bid = blockIdx.x;
    const int tid = threadIdx.x;
    const int k0 = (bid % (KDIM / TP_TILE)) * TP_TILE;
    const int d0 = (bid / (KDIM / TP_TILE)) * TP_TILE;
    const int tx = tid & 15;     // float4 lane along fast dim
    const int ty = tid >> 4;     // row 0..15

    #pragma unroll
    for (int i = 0; i < 4; ++i) {
        int r = ty + 16 * i;
        float4 v = __ldcs(reinterpret_cast<const float4*>(
            W + (size_t)(d0 + r) * KDIM + (k0 + 4 * tx)));
        t[r][4 * tx + 0] = v.x;
        t[r][4 * tx + 1] = v.y;
        t[r][4 * tx + 2] = v.z;
        t[r][4 * tx + 3] = v.w;
    }
    __syncthreads();

    #pragma unroll
    for (int i = 0; i < 4; ++i) {
        int r = ty + 16 * i;
        float4 v;
        v.x = t[4 * tx + 0][r];
        v.y = t[4 * tx + 1][r];
        v.z = t[4 * tx + 2][r];
        v.w = t[4 * tx + 3][r];
        *reinterpret_cast<float4*>(
            g_Wt + (size_t)(k0 + r) * DDIM + (d0 + 4 * tx)) = v;
    }
}

// ---------------- K2: 4 tokens per block, block-wide argmax ----------------
#define TOK_PER_BLOCK 4
__global__ void __launch_bounds__(256) argmax_gather_kernel(
    const float* __restrict__ x, float* __restrict__ out)
{
    const int nbase = blockIdx.x * TOK_PER_BLOCK;
    const int tid   = threadIdx.x;
    const int warp  = tid >> 5;
    const int lane  = tid & 31;

    __shared__ float s_val[8];
    __shared__ int   s_idx[8];
    __shared__ int   s_tok[TOK_PER_BLOCK];

    // ---- pre-barrier: argmax for 4 tokens (reads only x, overlaps K1) ----
    #pragma unroll
    for (int t = 0; t < TOK_PER_BLOCK; ++t) {
        const int n = nbase + t;
        const float4* xr = reinterpret_cast<const float4*>(x + (size_t)n * KDIM);

        float best = -FLT_MAX;
        int   bi   = 0x7fffffff;

        #pragma unroll
        for (int it = 0; it < (KDIM / 4) / 256; ++it) {
            int c = tid + it * 256;
            float4 v = __ldcs(xr + c);
            int base = c * 4;
            if (v.x > best) { best = v.x; bi = base + 0; }
            if (v.y > best) { best = v.y; bi = base + 1; }
            if (v.z > best) { best = v.z; bi = base + 2; }
            if (v.w > best) { best = v.w; bi = base + 3; }
        }

        // warp reduce (smaller index wins ties)
        #pragma unroll
        for (int off = 16; off > 0; off >>= 1) {
            float ov = __shfl_down_sync(0xffffffffu, best, off);
            int   oi = __shfl_down_sync(0xffffffffu, bi,   off);
            if (ov > best || (ov == best && oi < bi)) { best = ov; bi = oi; }
        }

        if (lane == 0) { s_val[warp] = best; s_idx[warp] = bi; }
        __syncthreads();
        if (warp == 0) {
            best = (lane < 8) ? s_val[lane] : -FLT_MAX;
            bi   = (lane < 8) ? s_idx[lane] : 0x7fffffff;
            #pragma unroll
            for (int off = 4; off > 0; off >>= 1) {
                float ov = __shfl_down_sync(0xffffffffu, best, off);
                int   oi = __shfl_down_sync(0xffffffffu, bi,   off);
                if (ov > best || (ov == best && oi < bi)) { best = ov; bi = oi; }
            }
            if (lane == 0) s_tok[t] = bi;
        }
        __syncthreads();   // smem reuse + s_tok visibility
    }

    // ---- wait for K1 (transpose) completion + memory flush ----
#if __CUDA_ARCH__ >= 900
    cudaGridDependencySynchronize();
#endif

    // ---- 4 coalesced row copies: out[n,:] = g_Wt[idx,:] ----
    #pragma unroll
    for (int t = 0; t < TOK_PER_BLOCK; ++t) {
        const int idx = s_tok[t];
        const float4* src = reinterpret_cast<const float4*>(g_Wt + (size_t)idx * DDIM);
        float4* dst = reinterpret_cast<float4*>(out + (size_t)(nbase + t) * DDIM);
        __stcs(dst + tid, src[tid]);
    }
}

extern "C" void kernel_launch(void* const* d_in, const int* in_sizes, int n_in,
                              void* d_out, int out_size) {
    const float* x = (const float*)d_in[0];   // [N, K]
    const float* W = (const float*)d_in[1];   // [D, K]
    float* out = (float*)d_out;               // [N, D]

    transpose_kernel<<<TP_BLOCKS, 256>>>(W);

    cudaLaunchConfig_t cfg = {};
    cfg.gridDim  = dim3(NTOK / TOK_PER_BLOCK, 1, 1);   // 2048
    cfg.blockDim = dim3(256, 1, 1);
    cfg.dynamicSmemBytes = 0;
    cfg.stream = 0;
    cudaLaunchAttribute attr[1];
    attr[0].id = cudaLaunchAttributeProgrammaticStreamSerialization;
    attr[0].val.programmaticStreamSerializationAllowed = 1;
    cfg.attrs = attr;
    cfg.numAttrs = 1;
    cudaLaunchKernelEx(&cfg, argmax_gather_kernel, x, out);
}

// round 12
// speedup vs baseline: 1.1342x; 1.1342x over previous
#include <cuda_runtime.h>
#include <cfloat>

// N=8192 tokens, K=4096, D=1024.
//   idx[n] = argmax_k x[n,k]  (first-occurrence tie-break)
//   out[n,d] = W[d, idx[n]]
//
// SINGLE kernel, 8192 blocks (token n = bid), 256 threads:
//   blocks 0..511 first transpose 2 tiles of W -> g_Wt (all wave-1 resident
//   at 8 blocks/SM, so no deadlock), release-fence + count into g_done.
//   Every block then runs the proven block-wide argmax on x[n,:] (__ldcs),
//   tid0-only acquire-polls g_done==512, __syncthreads, then the coalesced
//   gather out[n,:] = g_Wt[idx,:] (__stcs; Wt reads are L2 hits).
// Fixes R3's two measured failure causes: all-thread spin (LTS same-address
// hammering) and missing cache hints (Wt evicted by the x stream).
// Flags self-reset (last block) so graph replays start clean.

#define NTOK 8192
#define KDIM 4096
#define DDIM 1024
#define TP_TILE 64
#define TP_NTILES ((KDIM / TP_TILE) * (DDIM / TP_TILE))   // 1024
#define TP_PER_BLOCK 2
#define TP_OWNERS (TP_NTILES / TP_PER_BLOCK)              // 512 blocks

__device__ float g_Wt[(size_t)KDIM * DDIM];   // 16 MB scratch (L2-resident)
__device__ int   g_done = 0;                  // transpose blocks completed
__device__ int   g_fin  = 0;                  // blocks fully done (for reset)

__device__ __forceinline__ int ld_acquire_gpu(const int* p) {
    int v;
    asm volatile("ld.acquire.gpu.global.s32 %0, [%1];" : "=r"(v) : "l"(p) : "memory");
    return v;
}

__global__ void __launch_bounds__(256, 8) ste_kernel(
    const float* __restrict__ x, const float* __restrict__ W,
    float* __restrict__ out)
{
    const int bid = blockIdx.x;
    const int tid = threadIdx.x;
    const int warp = tid >> 5;
    const int lane = tid & 31;

    __shared__ float s_val[8];
    __shared__ int   s_idx[8];
    __shared__ int   s_final;

    // ---- blocks 0..511: transpose 2 tiles of W first (wave-1 resident) ----
    if (bid < TP_OWNERS) {
        __shared__ float t[TP_TILE][TP_TILE + 1];
        const int tx = tid & 15;     // float4 lane along fast dim
        const int ty = tid >> 4;     // row 0..15

        #pragma unroll
        for (int q = 0; q < TP_PER_BLOCK; ++q) {
            const int tile = bid * TP_PER_BLOCK + q;
            const int k0 = (tile % (KDIM / TP_TILE)) * TP_TILE;
            const int d0 = (tile / (KDIM / TP_TILE)) * TP_TILE;

            #pragma unroll
            for (int i = 0; i < 4; ++i) {
                int r = ty + 16 * i;
                float4 v = __ldcs(reinterpret_cast<const float4*>(
                    W + (size_t)(d0 + r) * KDIM + (k0 + 4 * tx)));
                t[r][4 * tx + 0] = v.x;
                t[r][4 * tx + 1] = v.y;
                t[r][4 * tx + 2] = v.z;
                t[r][4 * tx + 3] = v.w;
            }
            __syncthreads();

            #pragma unroll
            for (int i = 0; i < 4; ++i) {
                int r = ty + 16 * i;
                float4 v;
                v.x = t[4 * tx + 0][r];
                v.y = t[4 * tx + 1][r];
                v.z = t[4 * tx + 2][r];
                v.w = t[4 * tx + 3][r];
                *reinterpret_cast<float4*>(
                    g_Wt + (size_t)(k0 + r) * DDIM + (d0 + 4 * tx)) = v;
            }
            __syncthreads();
        }
        if (tid == 0) {
            __threadfence();             // release Wt stores
            atomicAdd(&g_done, 1);
        }
    }

    // ---- block-wide argmax over x[n, :] (R5's proven body) ----
    const int n = bid;
    const float4* xr = reinterpret_cast<const float4*>(x + (size_t)n * KDIM);
    float best = -FLT_MAX;
    int   bi   = 0x7fffffff;

    #pragma unroll
    for (int it = 0; it < (KDIM / 4) / 256; ++it) {
        int c = tid + it * 256;
        float4 v = __ldcs(xr + c);
        int base = c * 4;
        if (v.x > best) { best = v.x; bi = base + 0; }
        if (v.y > best) { best = v.y; bi = base + 1; }
        if (v.z > best) { best = v.z; bi = base + 2; }
        if (v.w > best) { best = v.w; bi = base + 3; }
    }

    // warp reduce (smaller index wins ties)
    #pragma unroll
    for (int off = 16; off > 0; off >>= 1) {
        float ov = __shfl_down_sync(0xffffffffu, best, off);
        int   oi = __shfl_down_sync(0xffffffffu, bi,   off);
        if (ov > best || (ov == best && oi < bi)) { best = ov; bi = oi; }
    }

    if (lane == 0) { s_val[warp] = best; s_idx[warp] = bi; }
    __syncthreads();
    if (warp == 0) {
        best = (lane < 8) ? s_val[lane] : -FLT_MAX;
        bi   = (lane < 8) ? s_idx[lane] : 0x7fffffff;
        #pragma unroll
        for (int off = 4; off > 0; off >>= 1) {
            float ov = __shfl_down_sync(0xffffffffu, best, off);
            int   oi = __shfl_down_sync(0xffffffffu, bi,   off);
            if (ov > best || (ov == best && oi < bi)) { best = ov; bi = oi; }
        }
        if (lane == 0) s_final = bi;
    }

    // ---- wait for all transposes: tid0-only poll, then block barrier ----
    if (tid == 0) {
        while (ld_acquire_gpu(&g_done) < TP_OWNERS) __nanosleep(128);
    }
    __syncthreads();                      // also publishes s_final
    const int idx = s_final;

    // ---- coalesced gather: out[n,:] = g_Wt[idx,:] (L2 hits) ----
    const float4* src = reinterpret_cast<const float4*>(g_Wt + (size_t)idx * DDIM);
    float4*       dst = reinterpret_cast<float4*>(out + (size_t)n * DDIM);
    __stcs(dst + tid, src[tid]);

    // ---- self-reset for graph replay (all waits passed before reset) ----
    __syncthreads();
    if (tid == 0) {
        int t = atomicAdd(&g_fin, 1);
        if (t == NTOK - 1) {
            atomicExch(&g_fin, 0);
            atomicExch(&g_done, 0);
        }
    }
}

extern "C" void kernel_launch(void* const* d_in, const int* in_sizes, int n_in,
                              void* d_out, int out_size) {
    const float* x = (const float*)d_in[0];   // [N, K]
    const float* W = (const float*)d_in[1];   // [D, K]
    float* out = (float*)d_out;               // [N, D]

    ste_kernel<<<NTOK, 256>>>(x, W, out);
}